// round 13
// baseline (speedup 1.0000x reference)
#include <cuda_runtime.h>
#include <math.h>

#define NN 64      // batch
#define TT 32      // timesteps
#define DA 1280    // feature channels
#define PP 16      // spatial positions (4x4)
#define HD 512     // hidden
#define WD 300     // wordvec
#define VV 32000   // vocab
#define FH 2048    // 4*HD

#define NBLK 64    // lstm barrier group
#define GRID_P 148 // persistent grid (all co-resident)
#define NTILES 2000 // 16 t-pairs x 125 col tiles

typedef unsigned int u32;
typedef unsigned long long u64;

// ---------------- scratch (device globals; no allocation allowed) -------------
__device__ float g_Aflat[NN * HD * PP];   // [n][h][p]
__device__ float g_h0[NN * HD];           // [n][h]
__device__ float g_xwx[NN * TT * FH];     // [n][t][4H]  (x@Wx + b)
__device__ float g_hn[NN * TT * HD];      // [n][t][h]
// packed bf16-split hcat: [n][kpair]; kp<256 = h, kp>=256 = attn
__device__ u32 g_hchi[NN * 512];
__device__ u32 g_hclo[NN * 512];
// pre-split, pre-transposed gate weights: [block b][jj 0..31][kpair 0..511]
__device__ u32 g_Wbhi[64 * 32 * 512];
__device__ u32 g_Wblo[64 * 32 * 512];
// xwx operand splits
__device__ u32 g_Xhi[2048 * 160];
__device__ u32 g_Xlo[2048 * 160];
__device__ u32 g_WXhi[2048 * 160];
__device__ u32 g_WXlo[2048 * 160];
__device__ unsigned g_bar_count;
__device__ volatile unsigned g_bar_gen;
__device__ int g_vwork;

// ---------------- helpers -----------------------------------------------------
__device__ __forceinline__ u32 pack_bf16(float x0, float x1) {
    u32 r;  // low half = x0, high half = x1
    asm("cvt.rn.bf16x2.f32 %0, %1, %2;" : "=r"(r) : "f"(x1), "f"(x0));
    return r;
}
__device__ __forceinline__ void split_pair(float x0, float x1, u32& hi, u32& lo) {
    hi = pack_bf16(x0, x1);
    float f0 = __uint_as_float(hi << 16);
    float f1 = __uint_as_float(hi & 0xffff0000u);
    lo = pack_bf16(x0 - f0, x1 - f1);
}
__device__ __forceinline__ u32 f2tf32(float x) {
    u32 r;
    asm("cvt.rna.tf32.f32 %0, %1;" : "=r"(r) : "f"(x));
    return r;
}
#define CP_ASYNC16(dst, src) \
    asm volatile("cp.async.cg.shared.global [%0], [%1], 16;" :: "r"(dst), "l"(src))
#define CP_COMMIT()  asm volatile("cp.async.commit_group;")
#define CP_WAIT0()   asm volatile("cp.async.wait_group 0;")

#define MMA_BF16(d0,d1,d2,d3,a0,a1,a2,a3,b0,b1) \
    asm volatile("mma.sync.aligned.m16n8k16.row.col.f32.bf16.bf16.f32 " \
        "{%0,%1,%2,%3}, {%4,%5,%6,%7}, {%8,%9}, {%0,%1,%2,%3};" \
        : "+f"(d0), "+f"(d1), "+f"(d2), "+f"(d3) \
        : "r"(a0), "r"(a1), "r"(a2), "r"(a3), "r"(b0), "r"(b1))

#define MMA_TF32(d0,d1,d2,d3,a0,a1,a2,a3,b0,b1) \
    asm volatile("mma.sync.aligned.m16n8k8.row.col.f32.tf32.tf32.f32 " \
        "{%0,%1,%2,%3}, {%4,%5,%6,%7}, {%8,%9}, {%0,%1,%2,%3};" \
        : "+f"(d0), "+f"(d1), "+f"(d2), "+f"(d3) \
        : "r"(a0), "r"(a1), "r"(a2), "r"(a3), "r"(b0), "r"(b1))

#define LDSM4(r0,r1,r2,r3,addr) \
    asm volatile("ldmatrix.sync.aligned.m8n8.x4.shared.b16 {%0,%1,%2,%3}, [%4];" \
        : "=r"(r0), "=r"(r1), "=r"(r2), "=r"(r3) : "r"(addr))

// ---------------- grid barrier (nanosleep backoff — measured best) ------------
__device__ __forceinline__ void grid_bar(unsigned* gen_local) {
    __syncthreads();
    if (threadIdx.x == 0) {
        unsigned gen = *gen_local;
        __threadfence();
        if (atomicAdd(&g_bar_count, 1u) == NBLK - 1u) {
            g_bar_count = 0u;
            __threadfence();
            g_bar_gen = gen + 1u;
        } else {
            while (g_bar_gen == gen) { __nanosleep(32); }
        }
        __threadfence();
        *gen_local = gen + 1u;
    }
    __syncthreads();
}

// ---------------- fused prep: conv | wprep | xprep | wxprep -------------------
// blocks 0..511 conv; 512..1535 wprep; 1536..1791 xprep; 1792..2047 wxprep
__global__ void prep_all_kernel(const float* __restrict__ A,
                                const float* __restrict__ cw,
                                const float* __restrict__ cb,
                                const float* __restrict__ Wh,
                                const float* __restrict__ Wattn,
                                const int* __restrict__ cap,
                                const float* __restrict__ We,
                                const float* __restrict__ Wx) {
    const int bid = blockIdx.x;
    const int tid = threadIdx.x;
    if (bid == 0 && tid == 0) {
        g_bar_count = 0u;
        g_bar_gen = 0u;
        g_vwork = 0;
    }

    if (bid < 512) {
        // ---- conv: n = bid&63, h-tile = bid>>6 ----
        int n = bid & 63;
        int hb0 = (bid >> 6) * 64;
        __shared__ float As[32][PP];
        __shared__ float Ws[64][32];
        int p = tid & 15;
        int hq = tid >> 4;
        float acc[4] = {0.f, 0.f, 0.f, 0.f};

        for (int c0 = 0; c0 < DA; c0 += 32) {
            {
                int idx = tid * 2;
                int c = idx >> 4, pp = idx & 15;
                const float* src = A + (size_t)(n * DA + c0 + c) * PP + pp;
                As[c][pp]     = src[0];
                As[c][pp + 1] = src[1];
            }
            {
                int hh = tid >> 2;
                int cc = (tid & 3) * 8;
                const float* src = cw + (size_t)(hb0 + hh) * DA + c0 + cc;
                #pragma unroll
                for (int i = 0; i < 8; i++) Ws[hh][cc + i] = src[i];
            }
            __syncthreads();
            #pragma unroll 8
            for (int c = 0; c < 32; c++) {
                float av = As[c][p];
                #pragma unroll
                for (int i = 0; i < 4; i++) acc[i] += Ws[hq * 4 + i][c] * av;
            }
            __syncthreads();
        }
        float mean4[4];
        #pragma unroll
        for (int i = 0; i < 4; i++) {
            int h = hb0 + hq * 4 + i;
            float v = acc[i] + cb[h];
            g_Aflat[(size_t)(n * HD + h) * PP + p] = v;
            float s = v;
            #pragma unroll
            for (int m = 1; m < 16; m <<= 1) s += __shfl_xor_sync(0xffffffffu, s, m);
            mean4[i] = s * (1.0f / 16.0f);
        }
        if (p == 0) {
            int h0i = hb0 + hq * 4;
            g_h0[n * HD + h0i + 0] = mean4[0];
            g_h0[n * HD + h0i + 1] = mean4[1];
            g_h0[n * HD + h0i + 2] = mean4[2];
            g_h0[n * HD + h0i + 3] = mean4[3];
            u32 hi, lo;
            split_pair(mean4[0], mean4[1], hi, lo);
            g_hchi[n * 512 + (h0i >> 1)] = hi;
            g_hclo[n * 512 + (h0i >> 1)] = lo;
            split_pair(mean4[2], mean4[3], hi, lo);
            g_hchi[n * 512 + (h0i >> 1) + 1] = hi;
            g_hclo[n * 512 + (h0i >> 1) + 1] = lo;
        }
    } else if (bid < 1536) {
        // ---- wprep: split + transpose Wh/Wattn into per-block layout ----
        __shared__ float Wt[64][36];
        int q = bid - 512;
        const int b = q & 63;
        const int ch = q >> 6;
        {
            int kk = tid >> 2;
            int g = tid & 3;
            const float* src = (ch < 8)
                ? (Wh + (size_t)(ch * 64 + kk) * FH + g * HD + b * 8)
                : (Wattn + (size_t)((ch - 8) * 64 + kk) * FH + g * HD + b * 8);
            float4 v0 = *(const float4*)(src);
            float4 v1 = *(const float4*)(src + 4);
            *(float4*)&Wt[kk][g * 8]     = v0;
            *(float4*)&Wt[kk][g * 8 + 4] = v1;
        }
        __syncthreads();
        {
            int jj = tid >> 3;
            int kpl = (tid & 7) * 4;
            uint4 vh, vl;
            u32* ph = (u32*)&vh;
            u32* pl = (u32*)&vl;
            #pragma unroll
            for (int qq = 0; qq < 4; qq++) {
                int kp = kpl + qq;
                float x0 = Wt[2 * kp][jj];
                float x1 = Wt[2 * kp + 1][jj];
                split_pair(x0, x1, ph[qq], pl[qq]);
            }
            size_t dst = (size_t)(b * 32 + jj) * 512 + ch * 32 + kpl;
            *(uint4*)(g_Wbhi + dst) = vh;
            *(uint4*)(g_Wblo + dst) = vl;
        }
    } else if (bid < 1792) {
        // ---- xprep ----
        int gid = (bid - 1536) * 256 + tid;
        for (int idx = gid; idx < 2048 * 160; idx += 65536) {
            int row = idx / 160, kp = idx % 160;
            int k0 = kp * 2;
            int c = cap[row];
            float x0 = (k0 < WD) ? We[(size_t)c * WD + k0] : 0.f;
            float x1 = (k0 + 1 < WD) ? We[(size_t)c * WD + k0 + 1] : 0.f;
            u32 hi, lo;
            split_pair(x0, x1, hi, lo);
            g_Xhi[idx] = hi;
            g_Xlo[idx] = lo;
        }
    } else {
        // ---- wxprep ----
        int gid = (bid - 1792) * 256 + tid;
        for (int idx = gid; idx < 2048 * 160; idx += 65536) {
            int kp = idx / 2048, j = idx % 2048;
            int k0 = kp * 2;
            float x0 = (k0 < WD) ? Wx[(size_t)k0 * FH + j] : 0.f;
            float x1 = (k0 + 1 < WD) ? Wx[(size_t)(k0 + 1) * FH + j] : 0.f;
            u32 hi, lo;
            split_pair(x0, x1, hi, lo);
            g_WXhi[j * 160 + kp] = hi;
            g_WXlo[j * 160 + kp] = lo;
        }
    }
}

// ---------------- xwx = X @ Wx + b via bf16x3 mma ----------------------------
#define XA_HI 0
#define XA_LO 5632
#define XB_HI 11264
#define XB_LO 16896
#define XWX_SMEM (22528 * 4)

__global__ __launch_bounds__(256, 1)
void xwx_mma_kernel(const float* __restrict__ bias) {
    extern __shared__ u32 xsm[];
    const int tid = threadIdx.x;
    const int bn = blockIdx.x, bm = blockIdx.y;
    const int warp = tid >> 5, lane = tid & 31;
    const int wm2 = (warp & 1) * 64;
    const int wn2 = (warp >> 1) * 32;
    const int gr = lane >> 2, ct = lane & 3;

    float acc[4][4][4];
    #pragma unroll
    for (int i = 0; i < 4; i++)
        #pragma unroll
        for (int j = 0; j < 4; j++)
            #pragma unroll
            for (int q = 0; q < 4; q++) acc[i][j][q] = 0.f;

    const int srow = tid >> 1;
    const int skq  = (tid & 1) * 20;
    const u32* aH = g_Xhi  + (size_t)(bm * 128 + srow) * 160 + skq;
    const u32* aL = g_Xlo  + (size_t)(bm * 128 + srow) * 160 + skq;
    const u32* bH = g_WXhi + (size_t)(bn * 128 + srow) * 160 + skq;
    const u32* bL = g_WXlo + (size_t)(bn * 128 + srow) * 160 + skq;

    for (int it = 0; it < 4; ++it) {
        #pragma unroll
        for (int q = 0; q < 5; q++) {
            int so = it * 40 + q * 4;
            int dof = srow * 44 + skq + q * 4;
            *(uint4*)&xsm[XA_HI + dof] = *(const uint4*)(aH + so);
            *(uint4*)&xsm[XA_LO + dof] = *(const uint4*)(aL + so);
            *(uint4*)&xsm[XB_HI + dof] = *(const uint4*)(bH + so);
            *(uint4*)&xsm[XB_LO + dof] = *(const uint4*)(bL + so);
        }
        __syncthreads();
        #pragma unroll
        for (int q = 0; q < 5; q++) {
            const int kb = q * 8 + ct;
            u32 ah[4][4], al[4][4];
            #pragma unroll
            for (int i = 0; i < 4; i++) {
                int base = (wm2 + i * 16 + gr) * 44 + kb;
                ah[i][0] = xsm[XA_HI + base];
                ah[i][1] = xsm[XA_HI + base + 8 * 44];
                ah[i][2] = xsm[XA_HI + base + 4];
                ah[i][3] = xsm[XA_HI + base + 8 * 44 + 4];
                al[i][0] = xsm[XA_LO + base];
                al[i][1] = xsm[XA_LO + base + 8 * 44];
                al[i][2] = xsm[XA_LO + base + 4];
                al[i][3] = xsm[XA_LO + base + 8 * 44 + 4];
            }
            #pragma unroll
            for (int j = 0; j < 4; j++) {
                int bbse = (wn2 + j * 8 + gr) * 44 + kb;
                u32 bh0 = xsm[XB_HI + bbse], bh1 = xsm[XB_HI + bbse + 4];
                u32 bl0 = xsm[XB_LO + bbse], bl1 = xsm[XB_LO + bbse + 4];
                #pragma unroll
                for (int i = 0; i < 4; i++) {
                    MMA_BF16(acc[i][j][0], acc[i][j][1], acc[i][j][2], acc[i][j][3],
                             ah[i][0], ah[i][1], ah[i][2], ah[i][3], bh0, bh1);
                    MMA_BF16(acc[i][j][0], acc[i][j][1], acc[i][j][2], acc[i][j][3],
                             ah[i][0], ah[i][1], ah[i][2], ah[i][3], bl0, bl1);
                    MMA_BF16(acc[i][j][0], acc[i][j][1], acc[i][j][2], acc[i][j][3],
                             al[i][0], al[i][1], al[i][2], al[i][3], bh0, bh1);
                }
            }
        }
        __syncthreads();
    }

    #pragma unroll
    for (int i = 0; i < 4; i++) {
        const int r0 = bm * 128 + wm2 + i * 16 + gr;
        #pragma unroll
        for (int j = 0; j < 4; j++) {
            const int col = bn * 128 + wn2 + j * 8 + ct * 2;
            const float b0 = bias[col], b1 = bias[col + 1];
            float2 v0 = {acc[i][j][0] + b0, acc[i][j][1] + b1};
            float2 v1 = {acc[i][j][2] + b0, acc[i][j][3] + b1};
            *(float2*)(g_xwx + (size_t)r0 * FH + col) = v0;
            *(float2*)(g_xwx + (size_t)(r0 + 8) * FH + col) = v1;
        }
    }
}

// ---------------- vocab tile: 128 rows (t-pair) x 256 cols, tf32 mma ----------
// 16 warps: 4M x 4N, warp tile 32x64 (acc[2][8][4] = 64 regs)
#define VAS(bu, m, k) vsm[(bu) * (128 * 20) + (m) * 20 + (k)]
#define VBS(bu, k, n) vsm[2 * 128 * 20 + (bu) * (16 * 264) + (k) * 264 + (n)]

__device__ void vocab_tile(float* vsm, int tp, int c,
                           const float* __restrict__ Wv,
                           const float* __restrict__ bv,
                           float* __restrict__ out, int tid) {
    const int warp = tid >> 5, lane = tid & 31;
    const int wm = (warp & 3) * 32;
    const int wn = (warp >> 2) * 64;
    const int gr = lane >> 2, ct = lane & 3;

    float acc[2][8][4];
    #pragma unroll
    for (int i = 0; i < 2; i++)
        #pragma unroll
        for (int j = 0; j < 8; j++)
            #pragma unroll
            for (int q = 0; q < 4; q++) acc[i][j][q] = 0.f;

    // staging maps (512 threads)
    const int arow = tid >> 2;             // 0..127 local row
    const int akq  = (tid & 3) * 4;        // k quad
    const int an   = arow & 63;
    const int adt  = arow >> 6;
    const float* aptr = g_hn + (size_t)(an * TT + 2 * tp + adt) * HD + akq;
    const int bk = tid >> 5;               // 0..15
    const int bn = lane * 8;               // 0..248
    const float* bptr = Wv + (size_t)bk * VV + c * 256 + bn;

    float4 ar, br0, br1;
    ar  = *(const float4*)(aptr);
    br0 = *(const float4*)(bptr);
    br1 = *(const float4*)(bptr + 4);
    {
        float4 w;
        w.x = __uint_as_float(f2tf32(ar.x)); w.y = __uint_as_float(f2tf32(ar.y));
        w.z = __uint_as_float(f2tf32(ar.z)); w.w = __uint_as_float(f2tf32(ar.w));
        *(float4*)&VAS(0, arow, akq) = w;
        w.x = __uint_as_float(f2tf32(br0.x)); w.y = __uint_as_float(f2tf32(br0.y));
        w.z = __uint_as_float(f2tf32(br0.z)); w.w = __uint_as_float(f2tf32(br0.w));
        *(float4*)&VBS(0, bk, bn) = w;
        w.x = __uint_as_float(f2tf32(br1.x)); w.y = __uint_as_float(f2tf32(br1.y));
        w.z = __uint_as_float(f2tf32(br1.z)); w.w = __uint_as_float(f2tf32(br1.w));
        *(float4*)&VBS(0, bk, bn + 4) = w;
    }
    __syncthreads();

    for (int it = 0; it < 32; ++it) {
        if (it < 31) {
            int k0 = (it + 1) * 16;
            ar  = *(const float4*)(aptr + k0);
            br0 = *(const float4*)(bptr + (size_t)k0 * VV);
            br1 = *(const float4*)(bptr + (size_t)k0 * VV + 4);
        }
        const int cb = it & 1;
        #pragma unroll
        for (int ks = 0; ks < 2; ks++) {
            const int kb = ks * 8;
            u32 a[2][4], bb[8][2];
            #pragma unroll
            for (int i = 0; i < 2; i++) {
                const int mr = wm + i * 16 + gr;
                a[i][0] = __float_as_uint(VAS(cb, mr,     kb + ct));
                a[i][1] = __float_as_uint(VAS(cb, mr + 8, kb + ct));
                a[i][2] = __float_as_uint(VAS(cb, mr,     kb + ct + 4));
                a[i][3] = __float_as_uint(VAS(cb, mr + 8, kb + ct + 4));
            }
            #pragma unroll
            for (int j = 0; j < 8; j++) {
                const int nb = wn + j * 8 + gr;
                bb[j][0] = __float_as_uint(VBS(cb, kb + ct,     nb));
                bb[j][1] = __float_as_uint(VBS(cb, kb + ct + 4, nb));
            }
            #pragma unroll
            for (int i = 0; i < 2; i++)
                #pragma unroll
                for (int j = 0; j < 8; j++)
                    MMA_TF32(acc[i][j][0], acc[i][j][1], acc[i][j][2], acc[i][j][3],
                             a[i][0], a[i][1], a[i][2], a[i][3],
                             bb[j][0], bb[j][1]);
        }
        if (it < 31) {
            const int nb = (it + 1) & 1;
            float4 w;
            w.x = __uint_as_float(f2tf32(ar.x)); w.y = __uint_as_float(f2tf32(ar.y));
            w.z = __uint_as_float(f2tf32(ar.z)); w.w = __uint_as_float(f2tf32(ar.w));
            *(float4*)&VAS(nb, arow, akq) = w;
            w.x = __uint_as_float(f2tf32(br0.x)); w.y = __uint_as_float(f2tf32(br0.y));
            w.z = __uint_as_float(f2tf32(br0.z)); w.w = __uint_as_float(f2tf32(br0.w));
            *(float4*)&VBS(nb, bk, bn) = w;
            w.x = __uint_as_float(f2tf32(br1.x)); w.y = __uint_as_float(f2tf32(br1.y));
            w.z = __uint_as_float(f2tf32(br1.z)); w.w = __uint_as_float(f2tf32(br1.w));
            *(float4*)&VBS(nb, bk, bn + 4) = w;
        }
        __syncthreads();
    }

    // epilogue: local row lr -> global row (lr&63)*TT + 2*tp + (lr>>6)
    #pragma unroll
    for (int i = 0; i < 2; i++) {
        const int lr0 = wm + i * 16 + gr;
        const int lr1 = lr0 + 8;
        const int g0 = (lr0 & 63) * TT + 2 * tp + (lr0 >> 6);
        const int g1 = (lr1 & 63) * TT + 2 * tp + (lr1 >> 6);
        #pragma unroll
        for (int j = 0; j < 8; j++) {
            const int col = c * 256 + wn + j * 8 + ct * 2;
            const float b0 = bv[col], b1 = bv[col + 1];
            float2 v0 = {acc[i][j][0] + b0, acc[i][j][1] + b1};
            float2 v1 = {acc[i][j][2] + b0, acc[i][j][3] + b1};
            *(float2*)(out + (size_t)g0 * VV + col) = v0;
            *(float2*)(out + (size_t)g1 * VV + col) = v1;
        }
    }
}

// ---------------- persistent LSTM + vocab workers: 148 blocks x 512 threads ---
#define OFF_BHI  0
#define OFF_BLO  16512
#define OFF_AHI  33024          // 2 bufs x (64 x 68)
#define OFF_ALO  41728
#define OFF_CS   50432          // f32 [64][34]
#define OFF_CELL 52608
#define OFF_HS   53120
#define OFF_RED  53632
#define OFF_WSF  54144
#define OFF_VIDX 54156          // vocab work-index slot (post-lstm reuse)
#define LSTM_SMEM (54160 * 4)

__global__ __launch_bounds__(512, 1)
void lstm_vocab_kernel(const float* __restrict__ Wv,
                       const float* __restrict__ bv,
                       float* __restrict__ out) {
    extern __shared__ u32 smu[];
    float* smf = (float*)smu;
    const int bid = blockIdx.x;
    const int tid = threadIdx.x;
    const unsigned sbase = (unsigned)__cvta_generic_to_shared(smu);

    if (bid < NBLK) {
        // ======================= LSTM path =======================
        const int b = bid;
        const int warp = tid >> 5, lane = tid & 31;
        const int wm = (warp & 3) * 16;
        const int wn = (warp >> 2) * 8;
        const int gr = lane >> 2, ct = lane & 3;

        {
            const u32* srcH = g_Wbhi + (size_t)b * 16384;
            const u32* srcL = g_Wblo + (size_t)b * 16384;
            #pragma unroll
            for (int r = 0; r < 8; r++) {
                int idx = r * 2048 + tid * 4;
                int j = idx >> 9, kp = idx & 511;
                *(uint4*)(smu + OFF_BHI + j * 516 + kp) = *(const uint4*)(srcH + idx);
                *(uint4*)(smu + OFF_BLO + j * 516 + kp) = *(const uint4*)(srcL + idx);
            }
        }
        {
            int n = tid >> 3, hl = tid & 7;
            smf[OFF_CELL + tid] = g_h0[n * HD + b * 8 + hl];
        }
        __syncthreads();

        const int arow = tid >> 3;
        const int akq = (tid & 7) * 8;
        const u32* aSrcHi = g_hchi + arow * 512 + akq;
        const u32* aSrcLo = g_hclo + arow * 512 + akq;
        const unsigned aDstHi = sbase + (OFF_AHI + arow * 68 + akq) * 4;
        const unsigned aDstLo = sbase + (OFF_ALO + arow * 68 + akq) * 4;

        const int lrow = wm + ((lane >> 3) & 1) * 8 + (lane & 7);
        const int lkp = (lane >> 4) * 4;
        const unsigned aFragHi = sbase + (OFF_AHI + lrow * 68 + lkp) * 4;
        const unsigned aFragLo = sbase + (OFF_ALO + lrow * 68 + lkp) * 4;
        const int jrowH = OFF_BHI + (wn + gr) * 516;
        const int jrowL = OFF_BLO + (wn + gr) * 516;

        unsigned gen = 0;

        for (int t = 0; t < TT; t++) {
            // early prefetch of gemm chunk 0 (h-part of hcat, valid here)
            CP_ASYNC16(aDstHi, aSrcHi);
            CP_ASYNC16(aDstHi + 16, aSrcHi + 4);
            CP_ASYNC16(aDstLo, aSrcLo);
            CP_ASYNC16(aDstLo + 16, aSrcLo + 4);
            CP_COMMIT();

            // ---------- stage A: attention for n = b ----------
            {
                const int n = b;
                const float* hp = (t == 0) ? (g_h0 + n * HD)
                                           : (g_hn + (size_t)(n * TT + (t - 1)) * HD);
                smf[OFF_HS + tid] = hp[tid];
                __syncthreads();
                {
                    int p = tid & 15, sl = tid >> 4;
                    float s = 0.f;
                    const float* af = g_Aflat + (size_t)(n * HD + sl * 16) * PP + p;
                    const float* hv = &smf[OFF_HS + sl * 16];
                    #pragma unroll 4
                    for (int h = 0; h < 16; h++) s += hv[h] * af[h * PP];
                    smf[OFF_RED + sl * 16 + p] = s;
                }
                __syncthreads();
                if (tid < 32) {
                    int p = tid & 15, half = tid >> 4;
                    float s = 0.f;
                    #pragma unroll
                    for (int i = 0; i < 16; i++)
                        s += smf[OFF_RED + (half * 16 + i) * 16 + p];
                    s += __shfl_xor_sync(0xffffffffu, s, 16);
                    s *= 0.044194173824159216f;  // 1/sqrt(512)
                    float m = s;
                    #pragma unroll
                    for (int d = 1; d < 16; d <<= 1)
                        m = fmaxf(m, __shfl_xor_sync(0xffffffffu, m, d));
                    float e = expf(s - m);
                    float sum = e;
                    #pragma unroll
                    for (int d = 1; d < 16; d <<= 1)
                        sum += __shfl_xor_sync(0xffffffffu, sum, d);
                    if (half == 0) smf[OFF_WSF + p] = e / sum;
                }
                __syncthreads();
                if (tid < 256) {
                    float4 w0 = *(const float4*)&smf[OFF_WSF + 0];
                    float4 w1 = *(const float4*)&smf[OFF_WSF + 4];
                    float4 w2 = *(const float4*)&smf[OFF_WSF + 8];
                    float4 w3 = *(const float4*)&smf[OFF_WSF + 12];
                    float sv[2];
                    #pragma unroll
                    for (int r = 0; r < 2; r++) {
                        int h = tid * 2 + r;
                        const float4* af = (const float4*)(g_Aflat + (size_t)(n * HD + h) * PP);
                        float4 x0 = af[0], x1 = af[1], x2 = af[2], x3 = af[3];
                        sv[r] = x0.x * w0.x + x0.y * w0.y + x0.z * w0.z + x0.w * w0.w
                              + x1.x * w1.x + x1.y * w1.y + x1.z * w1.z + x1.w * w1.w
                              + x2.x * w2.x + x2.y * w2.y + x2.z * w2.z + x2.w * w2.w
                              + x3.x * w3.x + x3.y * w3.y + x3.z * w3.z + x3.w * w3.w;
                    }
                    u32 hi, lo;
                    split_pair(sv[0], sv[1], hi, lo);
                    g_hchi[n * 512 + 256 + tid] = hi;
                    g_hclo[n * 512 + 256 + tid] = lo;
                }
            }
            grid_bar(&gen);

            // ---------- stage B: C[64, 32] = hcat @ Wslice (bf16x3 mma) -------
            float acc0 = 0.f, acc1 = 0.f, acc2 = 0.f, acc3 = 0.f;

            for (int it = 0; it < 8; ++it) {
                CP_WAIT0();
                __syncthreads();
                if (it < 7) {
                    const unsigned bo = ((it + 1) & 1) * 17408u;
                    const u32* sh = aSrcHi + (it + 1) * 64;
                    const u32* sl = aSrcLo + (it + 1) * 64;
                    CP_ASYNC16(aDstHi + bo, sh);
                    CP_ASYNC16(aDstHi + bo + 16, sh + 4);
                    CP_ASYNC16(aDstLo + bo, sl);
                    CP_ASYNC16(aDstLo + bo + 16, sl + 4);
                    CP_COMMIT();
                }
                const unsigned bofs = (it & 1) * 17408u;
                const int kbase = it * 64;
                #pragma unroll
                for (int q = 0; q < 8; q++) {
                    u32 ah0, ah1, ah2, ah3, al0, al1, al2, al3;
                    LDSM4(ah0, ah1, ah2, ah3, aFragHi + bofs + q * 32);
                    LDSM4(al0, al1, al2, al3, aFragLo + bofs + q * 32);
                    const int kb = kbase + q * 8 + ct;
                    u32 bh0 = smu[jrowH + kb], bh1 = smu[jrowH + kb + 4];
                    u32 bl0 = smu[jrowL + kb], bl1 = smu[jrowL + kb + 4];
                    MMA_BF16(acc0, acc1, acc2, acc3, ah0, ah1, ah2, ah3, bh0, bh1);
                    MMA_BF16(acc0, acc1, acc2, acc3, ah0, ah1, ah2, ah3, bl0, bl1);
                    MMA_BF16(acc0, acc1, acc2, acc3, al0, al1, al2, al3, bh0, bh1);
                }
            }

            {
                float* C = &smf[OFF_CS];
                *(float2*)&C[(wm + gr) * 34 + wn + 2 * ct]     = make_float2(acc0, acc1);
                *(float2*)&C[(wm + gr + 8) * 34 + wn + 2 * ct] = make_float2(acc2, acc3);
            }
            __syncthreads();

            {
                const int n = tid >> 3, hl = tid & 7;
                const float* C = &smf[OFF_CS + n * 34];
                const float* xw = g_xwx + (size_t)(n * TT + t) * FH + b * 8 + hl;
                float ai  = C[hl]      + xw[0];
                float af_ = C[8 + hl]  + xw[HD];
                float ao  = C[16 + hl] + xw[2 * HD];
                float ag  = C[24 + hl] + xw[3 * HD];
                float ig = 1.f / (1.f + expf(-ai));
                float fg = 1.f / (1.f + expf(-af_));
                float og = 1.f / (1.f + expf(-ao));
                float gg = tanhf(ag);
                float c = fg * smf[OFF_CELL + tid] + ig * gg;
                smf[OFF_CELL + tid] = c;
                float h = og * tanhf(c);
                g_hn[(size_t)(n * TT + t) * HD + b * 8 + hl] = h;
                float h1 = __shfl_down_sync(0xffffffffu, h, 1);
                if ((hl & 1) == 0) {
                    u32 hi, lo;
                    split_pair(h, h1, hi, lo);
                    int kp = b * 4 + (hl >> 1);
                    g_hchi[n * 512 + kp] = hi;
                    g_hclo[n * 512 + kp] = lo;
                }
            }
            grid_bar(&gen);
        }
        __syncthreads();
    }

    // ======================= vocab worker loop =======================
    int* s_idx = (int*)(smu + OFF_VIDX);
    for (;;) {
        if (tid == 0) *s_idx = atomicAdd(&g_vwork, 1);
        __syncthreads();
        int idx = *s_idx;
        __syncthreads();
        if (idx >= NTILES) break;
        int tp = idx / 125;
        int c  = idx - tp * 125;
        if (tid == 0) {
            unsigned need = 4u * tp + 4u;   // both steps of the pair committed
            while (g_bar_gen < need) { __nanosleep(128); }
        }
        __syncthreads();
        __threadfence();
        vocab_tile((float*)smu, tp, c, Wv, bv, out, tid);
        __syncthreads();
    }
}

// ---------------- launch ------------------------------------------------------
extern "C" void kernel_launch(void* const* d_in, const int* in_sizes, int n_in,
                              void* d_out, int out_size) {
    const float* A      = (const float*)d_in[0];
    const int*   cap    = (const int*)d_in[1];
    const float* conv_w = (const float*)d_in[2];
    const float* conv_b = (const float*)d_in[3];
    const float* Wx     = (const float*)d_in[4];
    const float* Wh     = (const float*)d_in[5];
    const float* Wattn  = (const float*)d_in[6];
    const float* b      = (const float*)d_in[7];
    const float* We     = (const float*)d_in[8];
    const float* Wv     = (const float*)d_in[9];
    const float* bv     = (const float*)d_in[10];
    float* out = (float*)d_out;

    cudaFuncSetAttribute(lstm_vocab_kernel,
                         cudaFuncAttributeMaxDynamicSharedMemorySize, LSTM_SMEM);
    cudaFuncSetAttribute(xwx_mma_kernel,
                         cudaFuncAttributeMaxDynamicSharedMemorySize, XWX_SMEM);

    prep_all_kernel<<<2048, 256>>>(A, conv_w, conv_b, Wh, Wattn, cap, We, Wx);
    xwx_mma_kernel<<<dim3(16, 16), 256, XWX_SMEM>>>(b);
    lstm_vocab_kernel<<<GRID_P, 512, LSTM_SMEM>>>(Wv, bv, out);
}

// round 14
// speedup vs baseline: 1.2592x; 1.2592x over previous
#include <cuda_runtime.h>
#include <math.h>

#define NN 64      // batch
#define TT 32      // timesteps
#define DA 1280    // feature channels
#define PP 16      // spatial positions (4x4)
#define HD 512     // hidden
#define WD 300     // wordvec
#define VV 32000   // vocab
#define FH 2048    // 4*HD

#define NBLK 64    // lstm barrier group
#define GRID_P 148 // persistent grid (all co-resident)
#define NTILES 2000 // 16 t-pairs x 125 col tiles

typedef unsigned int u32;
typedef unsigned long long u64;

// ---------------- scratch (device globals; no allocation allowed) -------------
__device__ float g_Aflat[NN * HD * PP];   // [n][h][p]
__device__ float g_h0[NN * HD];           // [n][h]
__device__ float g_xwx[NN * TT * FH];     // [n][t][4H]  (x@Wx + b)
__device__ float g_hn[NN * TT * HD];      // [n][t][h]
// packed bf16-split hcat: [n][kpair]; kp<256 = h, kp>=256 = attn
__device__ u32 g_hchi[NN * 512];
__device__ u32 g_hclo[NN * 512];
// pre-split, pre-transposed gate weights: [block b][jj 0..31][kpair 0..511]
__device__ u32 g_Wbhi[64 * 32 * 512];
__device__ u32 g_Wblo[64 * 32 * 512];
// xwx operand splits
__device__ u32 g_Xhi[2048 * 160];
__device__ u32 g_Xlo[2048 * 160];
__device__ u32 g_WXhi[2048 * 160];
__device__ u32 g_WXlo[2048 * 160];
// conv operand splits: A [row=(n,p) 1024][kp 640]; cw [h 512][kp 640]
__device__ u32 g_CAhi[1024 * 640];
__device__ u32 g_CAlo[1024 * 640];
__device__ u32 g_CWhi[512 * 640];
__device__ u32 g_CWlo[512 * 640];
__device__ unsigned g_bar_count;
__device__ volatile unsigned g_bar_gen;
__device__ int g_vwork;

// ---------------- helpers -----------------------------------------------------
__device__ __forceinline__ u32 pack_bf16(float x0, float x1) {
    u32 r;  // low half = x0, high half = x1
    asm("cvt.rn.bf16x2.f32 %0, %1, %2;" : "=r"(r) : "f"(x1), "f"(x0));
    return r;
}
__device__ __forceinline__ void split_pair(float x0, float x1, u32& hi, u32& lo) {
    hi = pack_bf16(x0, x1);
    float f0 = __uint_as_float(hi << 16);
    float f1 = __uint_as_float(hi & 0xffff0000u);
    lo = pack_bf16(x0 - f0, x1 - f1);
}
__device__ __forceinline__ u32 f2tf32(float x) {
    u32 r;
    asm("cvt.rna.tf32.f32 %0, %1;" : "=r"(r) : "f"(x));
    return r;
}
#define CP_ASYNC16(dst, src) \
    asm volatile("cp.async.cg.shared.global [%0], [%1], 16;" :: "r"(dst), "l"(src))
#define CP_COMMIT()  asm volatile("cp.async.commit_group;")
#define CP_WAIT0()   asm volatile("cp.async.wait_group 0;")

#define MMA_BF16(d0,d1,d2,d3,a0,a1,a2,a3,b0,b1) \
    asm volatile("mma.sync.aligned.m16n8k16.row.col.f32.bf16.bf16.f32 " \
        "{%0,%1,%2,%3}, {%4,%5,%6,%7}, {%8,%9}, {%0,%1,%2,%3};" \
        : "+f"(d0), "+f"(d1), "+f"(d2), "+f"(d3) \
        : "r"(a0), "r"(a1), "r"(a2), "r"(a3), "r"(b0), "r"(b1))

#define MMA_TF32(d0,d1,d2,d3,a0,a1,a2,a3,b0,b1) \
    asm volatile("mma.sync.aligned.m16n8k8.row.col.f32.tf32.tf32.f32 " \
        "{%0,%1,%2,%3}, {%4,%5,%6,%7}, {%8,%9}, {%0,%1,%2,%3};" \
        : "+f"(d0), "+f"(d1), "+f"(d2), "+f"(d3) \
        : "r"(a0), "r"(a1), "r"(a2), "r"(a3), "r"(b0), "r"(b1))

#define LDSM4(r0,r1,r2,r3,addr) \
    asm volatile("ldmatrix.sync.aligned.m8n8.x4.shared.b16 {%0,%1,%2,%3}, [%4];" \
        : "=r"(r0), "=r"(r1), "=r"(r2), "=r"(r3) : "r"(addr))

// ---------------- grid barrier (nanosleep backoff — measured best) ------------
__device__ __forceinline__ void grid_bar(unsigned* gen_local) {
    __syncthreads();
    if (threadIdx.x == 0) {
        unsigned gen = *gen_local;
        __threadfence();
        if (atomicAdd(&g_bar_count, 1u) == NBLK - 1u) {
            g_bar_count = 0u;
            __threadfence();
            g_bar_gen = gen + 1u;
        } else {
            while (g_bar_gen == gen) { __nanosleep(32); }
        }
        __threadfence();
        *gen_local = gen + 1u;
    }
    __syncthreads();
}

// ---------------- fused prep: aprep | cwprep | wprep | xprep | wxprep --------
// 0..255 aprep; 256..511 cwprep; 512..1535 wprep; 1536..1791 xprep; 1792..2047 wxprep
__global__ void prep_all_kernel(const float* __restrict__ A,
                                const float* __restrict__ cw,
                                const float* __restrict__ Wh,
                                const float* __restrict__ Wattn,
                                const int* __restrict__ cap,
                                const float* __restrict__ We,
                                const float* __restrict__ Wx) {
    const int bid = blockIdx.x;
    const int tid = threadIdx.x;
    if (bid == 0 && tid == 0) {
        g_bar_count = 0u;
        g_bar_gen = 0u;
        g_vwork = 0;
    }

    if (bid < 256) {
        // ---- aprep: A[n][c][p] -> [row=(n*16+p)][kp] hi/lo ----
        int gid = bid * 256 + tid;
        for (int idx = gid; idx < 1024 * 640; idx += 65536) {
            int row = idx / 640, kp = idx % 640;
            int n = row >> 4, p = row & 15;
            const float* src = A + (size_t)n * (DA * PP) + (size_t)(2 * kp) * PP + p;
            float x0 = src[0];
            float x1 = src[PP];
            u32 hi, lo;
            split_pair(x0, x1, hi, lo);
            g_CAhi[idx] = hi;
            g_CAlo[idx] = lo;
        }
    } else if (bid < 512) {
        // ---- cwprep: cw[h][c] -> [h][kp] hi/lo ----
        int gid = (bid - 256) * 256 + tid;
        for (int idx = gid; idx < 512 * 640; idx += 65536) {
            int h = idx / 640, kp = idx % 640;
            const float2 v = *(const float2*)(cw + (size_t)h * DA + 2 * kp);
            u32 hi, lo;
            split_pair(v.x, v.y, hi, lo);
            g_CWhi[idx] = hi;
            g_CWlo[idx] = lo;
        }
    } else if (bid < 1536) {
        // ---- wprep ----
        __shared__ float Wt[64][36];
        int q = bid - 512;
        const int b = q & 63;
        const int ch = q >> 6;
        {
            int kk = tid >> 2;
            int g = tid & 3;
            const float* src = (ch < 8)
                ? (Wh + (size_t)(ch * 64 + kk) * FH + g * HD + b * 8)
                : (Wattn + (size_t)((ch - 8) * 64 + kk) * FH + g * HD + b * 8);
            float4 v0 = *(const float4*)(src);
            float4 v1 = *(const float4*)(src + 4);
            *(float4*)&Wt[kk][g * 8]     = v0;
            *(float4*)&Wt[kk][g * 8 + 4] = v1;
        }
        __syncthreads();
        {
            int jj = tid >> 3;
            int kpl = (tid & 7) * 4;
            uint4 vh, vl;
            u32* ph = (u32*)&vh;
            u32* pl = (u32*)&vl;
            #pragma unroll
            for (int qq = 0; qq < 4; qq++) {
                int kp = kpl + qq;
                float x0 = Wt[2 * kp][jj];
                float x1 = Wt[2 * kp + 1][jj];
                split_pair(x0, x1, ph[qq], pl[qq]);
            }
            size_t dst = (size_t)(b * 32 + jj) * 512 + ch * 32 + kpl;
            *(uint4*)(g_Wbhi + dst) = vh;
            *(uint4*)(g_Wblo + dst) = vl;
        }
    } else if (bid < 1792) {
        // ---- xprep ----
        int gid = (bid - 1536) * 256 + tid;
        for (int idx = gid; idx < 2048 * 160; idx += 65536) {
            int row = idx / 160, kp = idx % 160;
            int k0 = kp * 2;
            int c = cap[row];
            float x0 = (k0 < WD) ? We[(size_t)c * WD + k0] : 0.f;
            float x1 = (k0 + 1 < WD) ? We[(size_t)c * WD + k0 + 1] : 0.f;
            u32 hi, lo;
            split_pair(x0, x1, hi, lo);
            g_Xhi[idx] = hi;
            g_Xlo[idx] = lo;
        }
    } else {
        // ---- wxprep ----
        int gid = (bid - 1792) * 256 + tid;
        for (int idx = gid; idx < 2048 * 160; idx += 65536) {
            int kp = idx / 2048, j = idx % 2048;
            int k0 = kp * 2;
            float x0 = (k0 < WD) ? Wx[(size_t)k0 * FH + j] : 0.f;
            float x1 = (k0 + 1 < WD) ? Wx[(size_t)(k0 + 1) * FH + j] : 0.f;
            u32 hi, lo;
            split_pair(x0, x1, hi, lo);
            g_WXhi[j * 160 + kp] = hi;
            g_WXlo[j * 160 + kp] = lo;
        }
    }
}

// ---------------- mma_all: xwx (blocks 0..255) + conv (blocks 256..383) -------
#define XA_HI 0
#define XA_LO 5632
#define XB_HI 11264
#define XB_LO 16896
#define XWX_SMEM (22528 * 4)
// conv smem layout (same buffer): 4 arrays of 64 x 84
#define CA_HI 0
#define CA_LO 5376
#define CB_HI 10752
#define CB_LO 16128

__global__ __launch_bounds__(256, 1)
void mma_all_kernel(const float* __restrict__ bias) {
    extern __shared__ u32 xsm[];
    const int bid = blockIdx.x;
    const int tid = threadIdx.x;
    const int warp = tid >> 5, lane = tid & 31;
    const int gr = lane >> 2, ct = lane & 3;

    if (bid < 256) {
        // ======================= xwx GEMM =======================
        const int bn = bid & 15, bm = bid >> 4;
        const int wm2 = (warp & 1) * 64;
        const int wn2 = (warp >> 1) * 32;

        float acc[4][4][4];
        #pragma unroll
        for (int i = 0; i < 4; i++)
            #pragma unroll
            for (int j = 0; j < 4; j++)
                #pragma unroll
                for (int q = 0; q < 4; q++) acc[i][j][q] = 0.f;

        const int srow = tid >> 1;
        const int skq  = (tid & 1) * 20;
        const u32* aH = g_Xhi  + (size_t)(bm * 128 + srow) * 160 + skq;
        const u32* aL = g_Xlo  + (size_t)(bm * 128 + srow) * 160 + skq;
        const u32* bH = g_WXhi + (size_t)(bn * 128 + srow) * 160 + skq;
        const u32* bL = g_WXlo + (size_t)(bn * 128 + srow) * 160 + skq;

        for (int it = 0; it < 4; ++it) {
            #pragma unroll
            for (int q = 0; q < 5; q++) {
                int so = it * 40 + q * 4;
                int dof = srow * 44 + skq + q * 4;
                *(uint4*)&xsm[XA_HI + dof] = *(const uint4*)(aH + so);
                *(uint4*)&xsm[XA_LO + dof] = *(const uint4*)(aL + so);
                *(uint4*)&xsm[XB_HI + dof] = *(const uint4*)(bH + so);
                *(uint4*)&xsm[XB_LO + dof] = *(const uint4*)(bL + so);
            }
            __syncthreads();
            #pragma unroll
            for (int q = 0; q < 5; q++) {
                const int kb = q * 8 + ct;
                u32 ah[4][4], al[4][4];
                #pragma unroll
                for (int i = 0; i < 4; i++) {
                    int base = (wm2 + i * 16 + gr) * 44 + kb;
                    ah[i][0] = xsm[XA_HI + base];
                    ah[i][1] = xsm[XA_HI + base + 8 * 44];
                    ah[i][2] = xsm[XA_HI + base + 4];
                    ah[i][3] = xsm[XA_HI + base + 8 * 44 + 4];
                    al[i][0] = xsm[XA_LO + base];
                    al[i][1] = xsm[XA_LO + base + 8 * 44];
                    al[i][2] = xsm[XA_LO + base + 4];
                    al[i][3] = xsm[XA_LO + base + 8 * 44 + 4];
                }
                #pragma unroll
                for (int j = 0; j < 4; j++) {
                    int bbse = (wn2 + j * 8 + gr) * 44 + kb;
                    u32 bh0 = xsm[XB_HI + bbse], bh1 = xsm[XB_HI + bbse + 4];
                    u32 bl0 = xsm[XB_LO + bbse], bl1 = xsm[XB_LO + bbse + 4];
                    #pragma unroll
                    for (int i = 0; i < 4; i++) {
                        MMA_BF16(acc[i][j][0], acc[i][j][1], acc[i][j][2], acc[i][j][3],
                                 ah[i][0], ah[i][1], ah[i][2], ah[i][3], bh0, bh1);
                        MMA_BF16(acc[i][j][0], acc[i][j][1], acc[i][j][2], acc[i][j][3],
                                 ah[i][0], ah[i][1], ah[i][2], ah[i][3], bl0, bl1);
                        MMA_BF16(acc[i][j][0], acc[i][j][1], acc[i][j][2], acc[i][j][3],
                                 al[i][0], al[i][1], al[i][2], al[i][3], bh0, bh1);
                    }
                }
            }
            __syncthreads();
        }

        #pragma unroll
        for (int i = 0; i < 4; i++) {
            const int r0 = bm * 128 + wm2 + i * 16 + gr;
            #pragma unroll
            for (int j = 0; j < 4; j++) {
                const int col = bn * 128 + wn2 + j * 8 + ct * 2;
                const float b0 = bias[col], b1 = bias[col + 1];
                float2 v0 = {acc[i][j][0] + b0, acc[i][j][1] + b1};
                float2 v1 = {acc[i][j][2] + b0, acc[i][j][3] + b1};
                *(float2*)(g_xwx + (size_t)r0 * FH + col) = v0;
                *(float2*)(g_xwx + (size_t)(r0 + 8) * FH + col) = v1;
            }
        }
    } else {
        // ======================= conv GEMM: C[1024,512] ===================
        const int q0 = bid - 256;       // 0..127
        const int cm = q0 >> 3;         // 0..15 (row tiles of 64)
        const int cn = q0 & 7;          // 0..7  (col tiles of 64)
        const int wm2 = (warp & 1) * 32;
        const int wn2 = (warp >> 1) * 16;

        float acc[2][2][4];
        #pragma unroll
        for (int i = 0; i < 2; i++)
            #pragma unroll
            for (int j = 0; j < 2; j++)
                #pragma unroll
                for (int qq = 0; qq < 4; qq++) acc[i][j][qq] = 0.f;

        const int srow = tid >> 2;            // 0..63
        const int skq  = (tid & 3) * 20;      // 0,20,40,60
        const u32* aH = g_CAhi + (size_t)(cm * 64 + srow) * 640 + skq;
        const u32* aL = g_CAlo + (size_t)(cm * 64 + srow) * 640 + skq;
        const u32* bH = g_CWhi + (size_t)(cn * 64 + srow) * 640 + skq;
        const u32* bL = g_CWlo + (size_t)(cn * 64 + srow) * 640 + skq;

        for (int it = 0; it < 8; ++it) {
            #pragma unroll
            for (int q = 0; q < 5; q++) {
                int so = it * 80 + q * 4;
                int dof = srow * 84 + skq + q * 4;
                *(uint4*)&xsm[CA_HI + dof] = *(const uint4*)(aH + so);
                *(uint4*)&xsm[CA_LO + dof] = *(const uint4*)(aL + so);
                *(uint4*)&xsm[CB_HI + dof] = *(const uint4*)(bH + so);
                *(uint4*)&xsm[CB_LO + dof] = *(const uint4*)(bL + so);
            }
            __syncthreads();
            #pragma unroll
            for (int q = 0; q < 10; q++) {
                const int kb = q * 8 + ct;
                u32 ah[2][4], al[2][4];
                #pragma unroll
                for (int i = 0; i < 2; i++) {
                    int base = (wm2 + i * 16 + gr) * 84 + kb;
                    ah[i][0] = xsm[CA_HI + base];
                    ah[i][1] = xsm[CA_HI + base + 8 * 84];
                    ah[i][2] = xsm[CA_HI + base + 4];
                    ah[i][3] = xsm[CA_HI + base + 8 * 84 + 4];
                    al[i][0] = xsm[CA_LO + base];
                    al[i][1] = xsm[CA_LO + base + 8 * 84];
                    al[i][2] = xsm[CA_LO + base + 4];
                    al[i][3] = xsm[CA_LO + base + 8 * 84 + 4];
                }
                #pragma unroll
                for (int j = 0; j < 2; j++) {
                    int bbse = (wn2 + j * 8 + gr) * 84 + kb;
                    u32 bh0 = xsm[CB_HI + bbse], bh1 = xsm[CB_HI + bbse + 4];
                    u32 bl0 = xsm[CB_LO + bbse], bl1 = xsm[CB_LO + bbse + 4];
                    #pragma unroll
                    for (int i = 0; i < 2; i++) {
                        MMA_BF16(acc[i][j][0], acc[i][j][1], acc[i][j][2], acc[i][j][3],
                                 ah[i][0], ah[i][1], ah[i][2], ah[i][3], bh0, bh1);
                        MMA_BF16(acc[i][j][0], acc[i][j][1], acc[i][j][2], acc[i][j][3],
                                 ah[i][0], ah[i][1], ah[i][2], ah[i][3], bl0, bl1);
                        MMA_BF16(acc[i][j][0], acc[i][j][1], acc[i][j][2], acc[i][j][3],
                                 al[i][0], al[i][1], al[i][2], al[i][3], bh0, bh1);
                    }
                }
            }
            __syncthreads();
        }

        // epilogue: write g_Aflat[n][h][p] (+bias later? no: conv bias cb added in h0pack? No —
        // cb must be added here; it is passed via bias2 trick below.)
        // NOTE: cb is appended to the 'bias' pointer space by host: bias = b (FH floats),
        // conv bias lives at bias + FH.
        const float* cb = bias + FH;
        #pragma unroll
        for (int i = 0; i < 2; i++) {
            #pragma unroll
            for (int half = 0; half < 2; half++) {
                const int lr = cm * 64 + wm2 + i * 16 + gr + half * 8;
                const int n = lr >> 4, p = lr & 15;
                #pragma unroll
                for (int j = 0; j < 2; j++) {
                    const int h = cn * 64 + wn2 + j * 8 + ct * 2;
                    float v0 = acc[i][j][half * 2 + 0] + cb[h];
                    float v1 = acc[i][j][half * 2 + 1] + cb[h + 1];
                    g_Aflat[(size_t)(n * HD + h) * PP + p] = v0;
                    g_Aflat[(size_t)(n * HD + h + 1) * PP + p] = v1;
                }
            }
        }
    }
}

// ---------------- h0pack: means over p + pack h0 splits ------------------------
__global__ void h0pack_kernel() {
    const int n = blockIdx.x;
    const int tid = threadIdx.x;      // 256
    const int h = tid * 2;
    float m[2];
    #pragma unroll
    for (int r = 0; r < 2; r++) {
        const float4* src = (const float4*)(g_Aflat + (size_t)(n * HD + h + r) * PP);
        float4 a = src[0], bq = src[1], cq = src[2], d = src[3];
        float s = a.x + a.y + a.z + a.w + bq.x + bq.y + bq.z + bq.w
                + cq.x + cq.y + cq.z + cq.w + d.x + d.y + d.z + d.w;
        m[r] = s * (1.0f / 16.0f);
    }
    g_h0[n * HD + h] = m[0];
    g_h0[n * HD + h + 1] = m[1];
    u32 hi, lo;
    split_pair(m[0], m[1], hi, lo);
    g_hchi[n * 512 + tid] = hi;
    g_hclo[n * 512 + tid] = lo;
}

// ---------------- vocab tile: 128 rows (t-pair) x 256 cols, tf32 mma ----------
#define VAS(bu, m, k) vsm[(bu) * (128 * 20) + (m) * 20 + (k)]
#define VBS(bu, k, n) vsm[2 * 128 * 20 + (bu) * (16 * 264) + (k) * 264 + (n)]

__device__ void vocab_tile(float* vsm, int tp, int c,
                           const float* __restrict__ Wv,
                           const float* __restrict__ bv,
                           float* __restrict__ out, int tid) {
    const int warp = tid >> 5, lane = tid & 31;
    const int wm = (warp & 3) * 32;
    const int wn = (warp >> 2) * 64;
    const int gr = lane >> 2, ct = lane & 3;

    float acc[2][8][4];
    #pragma unroll
    for (int i = 0; i < 2; i++)
        #pragma unroll
        for (int j = 0; j < 8; j++)
            #pragma unroll
            for (int q = 0; q < 4; q++) acc[i][j][q] = 0.f;

    const int arow = tid >> 2;
    const int akq  = (tid & 3) * 4;
    const int an   = arow & 63;
    const int adt  = arow >> 6;
    const float* aptr = g_hn + (size_t)(an * TT + 2 * tp + adt) * HD + akq;
    const int bk = tid >> 5;
    const int bn = lane * 8;
    const float* bptr = Wv + (size_t)bk * VV + c * 256 + bn;

    float4 ar, br0, br1;
    ar  = *(const float4*)(aptr);
    br0 = *(const float4*)(bptr);
    br1 = *(const float4*)(bptr + 4);
    {
        float4 w;
        w.x = __uint_as_float(f2tf32(ar.x)); w.y = __uint_as_float(f2tf32(ar.y));
        w.z = __uint_as_float(f2tf32(ar.z)); w.w = __uint_as_float(f2tf32(ar.w));
        *(float4*)&VAS(0, arow, akq) = w;
        w.x = __uint_as_float(f2tf32(br0.x)); w.y = __uint_as_float(f2tf32(br0.y));
        w.z = __uint_as_float(f2tf32(br0.z)); w.w = __uint_as_float(f2tf32(br0.w));
        *(float4*)&VBS(0, bk, bn) = w;
        w.x = __uint_as_float(f2tf32(br1.x)); w.y = __uint_as_float(f2tf32(br1.y));
        w.z = __uint_as_float(f2tf32(br1.z)); w.w = __uint_as_float(f2tf32(br1.w));
        *(float4*)&VBS(0, bk, bn + 4) = w;
    }
    __syncthreads();

    for (int it = 0; it < 32; ++it) {
        if (it < 31) {
            int k0 = (it + 1) * 16;
            ar  = *(const float4*)(aptr + k0);
            br0 = *(const float4*)(bptr + (size_t)k0 * VV);
            br1 = *(const float4*)(bptr + (size_t)k0 * VV + 4);
        }
        const int cb = it & 1;
        #pragma unroll
        for (int ks = 0; ks < 2; ks++) {
            const int kb = ks * 8;
            u32 a[2][4], bb[8][2];
            #pragma unroll
            for (int i = 0; i < 2; i++) {
                const int mr = wm + i * 16 + gr;
                a[i][0] = __float_as_uint(VAS(cb, mr,     kb + ct));
                a[i][1] = __float_as_uint(VAS(cb, mr + 8, kb + ct));
                a[i][2] = __float_as_uint(VAS(cb, mr,     kb + ct + 4));
                a[i][3] = __float_as_uint(VAS(cb, mr + 8, kb + ct + 4));
            }
            #pragma unroll
            for (int j = 0; j < 8; j++) {
                const int nb = wn + j * 8 + gr;
                bb[j][0] = __float_as_uint(VBS(cb, kb + ct,     nb));
                bb[j][1] = __float_as_uint(VBS(cb, kb + ct + 4, nb));
            }
            #pragma unroll
            for (int i = 0; i < 2; i++)
                #pragma unroll
                for (int j = 0; j < 8; j++)
                    MMA_TF32(acc[i][j][0], acc[i][j][1], acc[i][j][2], acc[i][j][3],
                             a[i][0], a[i][1], a[i][2], a[i][3],
                             bb[j][0], bb[j][1]);
        }
        if (it < 31) {
            const int nb = (it + 1) & 1;
            float4 w;
            w.x = __uint_as_float(f2tf32(ar.x)); w.y = __uint_as_float(f2tf32(ar.y));
            w.z = __uint_as_float(f2tf32(ar.z)); w.w = __uint_as_float(f2tf32(ar.w));
            *(float4*)&VAS(nb, arow, akq) = w;
            w.x = __uint_as_float(f2tf32(br0.x)); w.y = __uint_as_float(f2tf32(br0.y));
            w.z = __uint_as_float(f2tf32(br0.z)); w.w = __uint_as_float(f2tf32(br0.w));
            *(float4*)&VBS(nb, bk, bn) = w;
            w.x = __uint_as_float(f2tf32(br1.x)); w.y = __uint_as_float(f2tf32(br1.y));
            w.z = __uint_as_float(f2tf32(br1.z)); w.w = __uint_as_float(f2tf32(br1.w));
            *(float4*)&VBS(nb, bk, bn + 4) = w;
        }
        __syncthreads();
    }

    #pragma unroll
    for (int i = 0; i < 2; i++) {
        const int lr0 = wm + i * 16 + gr;
        const int lr1 = lr0 + 8;
        const int g0 = (lr0 & 63) * TT + 2 * tp + (lr0 >> 6);
        const int g1 = (lr1 & 63) * TT + 2 * tp + (lr1 >> 6);
        #pragma unroll
        for (int j = 0; j < 8; j++) {
            const int col = c * 256 + wn + j * 8 + ct * 2;
            const float b0 = bv[col], b1 = bv[col + 1];
            float2 v0 = {acc[i][j][0] + b0, acc[i][j][1] + b1};
            float2 v1 = {acc[i][j][2] + b0, acc[i][j][3] + b1};
            *(float2*)(out + (size_t)g0 * VV + col) = v0;
            *(float2*)(out + (size_t)g1 * VV + col) = v1;
        }
    }
}

// ---------------- persistent LSTM + vocab workers: 148 blocks x 512 threads ---
#define OFF_BHI  0
#define OFF_BLO  16512
#define OFF_AHI  33024          // 2 bufs x (64 x 68)
#define OFF_ALO  41728
#define OFF_CS   50432          // f32 [64][34]
#define OFF_CELL 52608
#define OFF_HS   53120
#define OFF_RED  53632
#define OFF_WSF  54144
#define OFF_VIDX 54156          // vocab work-index slot (post-lstm reuse)
#define LSTM_SMEM (54160 * 4)

__global__ __launch_bounds__(512, 1)
void lstm_vocab_kernel(const float* __restrict__ Wv,
                       const float* __restrict__ bv,
                       float* __restrict__ out) {
    extern __shared__ u32 smu[];
    float* smf = (float*)smu;
    const int bid = blockIdx.x;
    const int tid = threadIdx.x;
    const unsigned sbase = (unsigned)__cvta_generic_to_shared(smu);

    if (bid < NBLK) {
        // ======================= LSTM path =======================
        const int b = bid;
        const int warp = tid >> 5, lane = tid & 31;
        const int wm = (warp & 3) * 16;
        const int wn = (warp >> 2) * 8;
        const int gr = lane >> 2, ct = lane & 3;

        {
            const u32* srcH = g_Wbhi + (size_t)b * 16384;
            const u32* srcL = g_Wblo + (size_t)b * 16384;
            #pragma unroll
            for (int r = 0; r < 8; r++) {
                int idx = r * 2048 + tid * 4;
                int j = idx >> 9, kp = idx & 511;
                *(uint4*)(smu + OFF_BHI + j * 516 + kp) = *(const uint4*)(srcH + idx);
                *(uint4*)(smu + OFF_BLO + j * 516 + kp) = *(const uint4*)(srcL + idx);
            }
        }
        {
            int n = tid >> 3, hl = tid & 7;
            smf[OFF_CELL + tid] = g_h0[n * HD + b * 8 + hl];
        }
        __syncthreads();

        const int arow = tid >> 3;
        const int akq = (tid & 7) * 8;
        const u32* aSrcHi = g_hchi + arow * 512 + akq;
        const u32* aSrcLo = g_hclo + arow * 512 + akq;
        const unsigned aDstHi = sbase + (OFF_AHI + arow * 68 + akq) * 4;
        const unsigned aDstLo = sbase + (OFF_ALO + arow * 68 + akq) * 4;

        const int lrow = wm + ((lane >> 3) & 1) * 8 + (lane & 7);
        const int lkp = (lane >> 4) * 4;
        const unsigned aFragHi = sbase + (OFF_AHI + lrow * 68 + lkp) * 4;
        const unsigned aFragLo = sbase + (OFF_ALO + lrow * 68 + lkp) * 4;
        const int jrowH = OFF_BHI + (wn + gr) * 516;
        const int jrowL = OFF_BLO + (wn + gr) * 516;

        unsigned gen = 0;

        for (int t = 0; t < TT; t++) {
            CP_ASYNC16(aDstHi, aSrcHi);
            CP_ASYNC16(aDstHi + 16, aSrcHi + 4);
            CP_ASYNC16(aDstLo, aSrcLo);
            CP_ASYNC16(aDstLo + 16, aSrcLo + 4);
            CP_COMMIT();

            // ---------- stage A: attention for n = b ----------
            {
                const int n = b;
                const float* hp = (t == 0) ? (g_h0 + n * HD)
                                           : (g_hn + (size_t)(n * TT + (t - 1)) * HD);
                smf[OFF_HS + tid] = hp[tid];
                __syncthreads();
                {
                    int p = tid & 15, sl = tid >> 4;
                    float s = 0.f;
                    const float* af = g_Aflat + (size_t)(n * HD + sl * 16) * PP + p;
                    const float* hv = &smf[OFF_HS + sl * 16];
                    #pragma unroll 4
                    for (int h = 0; h < 16; h++) s += hv[h] * af[h * PP];
                    smf[OFF_RED + sl * 16 + p] = s;
                }
                __syncthreads();
                if (tid < 32) {
                    int p = tid & 15, half = tid >> 4;
                    float s = 0.f;
                    #pragma unroll
                    for (int i = 0; i < 16; i++)
                        s += smf[OFF_RED + (half * 16 + i) * 16 + p];
                    s += __shfl_xor_sync(0xffffffffu, s, 16);
                    s *= 0.044194173824159216f;  // 1/sqrt(512)
                    float m = s;
                    #pragma unroll
                    for (int d = 1; d < 16; d <<= 1)
                        m = fmaxf(m, __shfl_xor_sync(0xffffffffu, m, d));
                    float e = expf(s - m);
                    float sum = e;
                    #pragma unroll
                    for (int d = 1; d < 16; d <<= 1)
                        sum += __shfl_xor_sync(0xffffffffu, sum, d);
                    if (half == 0) smf[OFF_WSF + p] = e / sum;
                }
                __syncthreads();
                if (tid < 256) {
                    float4 w0 = *(const float4*)&smf[OFF_WSF + 0];
                    float4 w1 = *(const float4*)&smf[OFF_WSF + 4];
                    float4 w2 = *(const float4*)&smf[OFF_WSF + 8];
                    float4 w3 = *(const float4*)&smf[OFF_WSF + 12];
                    float sv[2];
                    #pragma unroll
                    for (int r = 0; r < 2; r++) {
                        int h = tid * 2 + r;
                        const float4* af = (const float4*)(g_Aflat + (size_t)(n * HD + h) * PP);
                        float4 x0 = af[0], x1 = af[1], x2 = af[2], x3 = af[3];
                        sv[r] = x0.x * w0.x + x0.y * w0.y + x0.z * w0.z + x0.w * w0.w
                              + x1.x * w1.x + x1.y * w1.y + x1.z * w1.z + x1.w * w1.w
                              + x2.x * w2.x + x2.y * w2.y + x2.z * w2.z + x2.w * w2.w
                              + x3.x * w3.x + x3.y * w3.y + x3.z * w3.z + x3.w * w3.w;
                    }
                    u32 hi, lo;
                    split_pair(sv[0], sv[1], hi, lo);
                    g_hchi[n * 512 + 256 + tid] = hi;
                    g_hclo[n * 512 + 256 + tid] = lo;
                }
            }
            grid_bar(&gen);

            // ---------- stage B: C[64, 32] = hcat @ Wslice (bf16x3 mma) -------
            float acc0 = 0.f, acc1 = 0.f, acc2 = 0.f, acc3 = 0.f;

            for (int it = 0; it < 8; ++it) {
                CP_WAIT0();
                __syncthreads();
                if (it < 7) {
                    const unsigned bo = ((it + 1) & 1) * 17408u;
                    const u32* sh = aSrcHi + (it + 1) * 64;
                    const u32* sl = aSrcLo + (it + 1) * 64;
                    CP_ASYNC16(aDstHi + bo, sh);
                    CP_ASYNC16(aDstHi + bo + 16, sh + 4);
                    CP_ASYNC16(aDstLo + bo, sl);
                    CP_ASYNC16(aDstLo + bo + 16, sl + 4);
                    CP_COMMIT();
                }
                const unsigned bofs = (it & 1) * 17408u;
                const int kbase = it * 64;
                #pragma unroll
                for (int q = 0; q < 8; q++) {
                    u32 ah0, ah1, ah2, ah3, al0, al1, al2, al3;
                    LDSM4(ah0, ah1, ah2, ah3, aFragHi + bofs + q * 32);
                    LDSM4(al0, al1, al2, al3, aFragLo + bofs + q * 32);
                    const int kb = kbase + q * 8 + ct;
                    u32 bh0 = smu[jrowH + kb], bh1 = smu[jrowH + kb + 4];
                    u32 bl0 = smu[jrowL + kb], bl1 = smu[jrowL + kb + 4];
                    MMA_BF16(acc0, acc1, acc2, acc3, ah0, ah1, ah2, ah3, bh0, bh1);
                    MMA_BF16(acc0, acc1, acc2, acc3, ah0, ah1, ah2, ah3, bl0, bl1);
                    MMA_BF16(acc0, acc1, acc2, acc3, al0, al1, al2, al3, bh0, bh1);
                }
            }

            {
                float* C = &smf[OFF_CS];
                *(float2*)&C[(wm + gr) * 34 + wn + 2 * ct]     = make_float2(acc0, acc1);
                *(float2*)&C[(wm + gr + 8) * 34 + wn + 2 * ct] = make_float2(acc2, acc3);
            }
            __syncthreads();

            {
                const int n = tid >> 3, hl = tid & 7;
                const float* C = &smf[OFF_CS + n * 34];
                const float* xw = g_xwx + (size_t)(n * TT + t) * FH + b * 8 + hl;
                float ai  = C[hl]      + xw[0];
                float af_ = C[8 + hl]  + xw[HD];
                float ao  = C[16 + hl] + xw[2 * HD];
                float ag  = C[24 + hl] + xw[3 * HD];
                float ig = 1.f / (1.f + expf(-ai));
                float fg = 1.f / (1.f + expf(-af_));
                float og = 1.f / (1.f + expf(-ao));
                float gg = tanhf(ag);
                float c = fg * smf[OFF_CELL + tid] + ig * gg;
                smf[OFF_CELL + tid] = c;
                float h = og * tanhf(c);
                g_hn[(size_t)(n * TT + t) * HD + b * 8 + hl] = h;
                float h1 = __shfl_down_sync(0xffffffffu, h, 1);
                if ((hl & 1) == 0) {
                    u32 hi, lo;
                    split_pair(h, h1, hi, lo);
                    int kp = b * 4 + (hl >> 1);
                    g_hchi[n * 512 + kp] = hi;
                    g_hclo[n * 512 + kp] = lo;
                }
            }
            grid_bar(&gen);
        }
        __syncthreads();
    }

    // ======================= vocab worker loop =======================
    int* s_idx = (int*)(smu + OFF_VIDX);
    for (;;) {
        if (tid == 0) *s_idx = atomicAdd(&g_vwork, 1);
        __syncthreads();
        int idx = *s_idx;
        __syncthreads();
        if (idx >= NTILES) break;
        int tp = idx / 125;
        int c  = idx - tp * 125;
        if (tid == 0) {
            unsigned need = 4u * tp + 4u;   // both steps of the pair committed
            while (g_bar_gen < need) { __nanosleep(128); }
        }
        __syncthreads();
        __threadfence();
        vocab_tile((float*)smu, tp, c, Wv, bv, out, tid);
        __syncthreads();
    }
}

// ---------------- bias concat helper (b ++ conv_b into one buffer) ------------
__device__ float g_bias2[FH + HD];
__global__ void biascat_kernel(const float* __restrict__ b,
                               const float* __restrict__ cb) {
    int i = blockIdx.x * blockDim.x + threadIdx.x;
    if (i < FH) g_bias2[i] = b[i];
    else if (i < FH + HD) g_bias2[i] = cb[i - FH];
}

// ---------------- launch ------------------------------------------------------
extern "C" void kernel_launch(void* const* d_in, const int* in_sizes, int n_in,
                              void* d_out, int out_size) {
    const float* A      = (const float*)d_in[0];
    const int*   cap    = (const int*)d_in[1];
    const float* conv_w = (const float*)d_in[2];
    const float* conv_b = (const float*)d_in[3];
    const float* Wx     = (const float*)d_in[4];
    const float* Wh     = (const float*)d_in[5];
    const float* Wattn  = (const float*)d_in[6];
    const float* b      = (const float*)d_in[7];
    const float* We     = (const float*)d_in[8];
    const float* Wv     = (const float*)d_in[9];
    const float* bv     = (const float*)d_in[10];
    float* out = (float*)d_out;

    cudaFuncSetAttribute(lstm_vocab_kernel,
                         cudaFuncAttributeMaxDynamicSharedMemorySize, LSTM_SMEM);
    cudaFuncSetAttribute(mma_all_kernel,
                         cudaFuncAttributeMaxDynamicSharedMemorySize, XWX_SMEM);

    float* d_bias2;
    cudaGetSymbolAddress((void**)&d_bias2, g_bias2);

    biascat_kernel<<<10, 256>>>(b, conv_b);
    prep_all_kernel<<<2048, 256>>>(A, conv_w, Wh, Wattn, cap, We, Wx);
    mma_all_kernel<<<384, 256, XWX_SMEM>>>(d_bias2);
    h0pack_kernel<<<64, 256>>>();
    lstm_vocab_kernel<<<GRID_P, 512, LSTM_SMEM>>>(Wv, bv, out);
}